// round 4
// baseline (speedup 1.0000x reference)
#include <cuda_runtime.h>
#include <math.h>

// Problem constants (fixed by the reference: N=16384, S=6, C=101)
#define NCELLS  (16384 * 6 * 6)   // 589824 cells
#define CHANS   106               // 5 + C
#define NUNITS  (NCELLS / 2)      // 294912 two-cell units (848 B, 16B aligned)
#define UNIT_F  (2 * CHANS)       // 212 floats per unit
#define UNIT_P4 53                // float4 pairs per unit
#define NBLOCKS 1184              // 148 SMs x 8 blocks
#define NWPB    8                 // warps per block (256 threads)
#define BATCH   16384.0

// Per-block partial sums, SoA layout [channel][block]. Written unconditionally
// by every block -> no init kernel needed. (Device global: no allocs allowed.)
__device__ float g_part[5 * NBLOCKS];

__global__ void __launch_bounds__(256) yolo_reduce_kernel(
    const float* __restrict__ pred,
    const float* __restrict__ targ)
{
    __shared__ float s[NWPB][5];

    const int lane  = threadIdx.x & 31;
    const int wid   = threadIdx.x >> 5;
    const int gwarp = blockIdx.x * NWPB + wid;
    const int nwarp = NBLOCKS * NWPB;

    float sxy = 0.f, swh = 0.f, sco = 0.f, scn = 0.f, scl = 0.f;

    for (int unit = gwarp; unit < NUNITS; unit += nwarp) {
        const size_t base = (size_t)unit * UNIT_F;
        // object masks for the two cells in this unit (broadcast loads)
        const float obj0 = (__ldg(targ + base + 4)   != 0.f) ? 1.f : 0.f;
        const float obj1 = (__ldg(targ + base + 110) != 0.f) ? 1.f : 0.f;

        const float4* __restrict__ t4p = (const float4*)(targ + base);
        const float4* __restrict__ p4p = (const float4*)(pred + base);

        #pragma unroll
        for (int it = 0; it < 2; ++it) {
            const int p = lane + 32 * it;
            if (p < UNIT_P4) {
                const float4 tv = __ldg(t4p + p);
                const float4 pv = __ldg(p4p + p);
                const float te[4] = {tv.x, tv.y, tv.z, tv.w};
                const float pe[4] = {pv.x, pv.y, pv.z, pv.w};

                #pragma unroll
                for (int e = 0; e < 4; ++e) {
                    // idx, second, ch are functions of lane only -> loop-invariant
                    // predicates after LICM; the body is predicated FFMAs.
                    const int   idx    = 4 * p + e;
                    const bool  second = (idx >= CHANS);
                    const int   ch     = second ? idx - CHANS : idx;
                    const float obj    = second ? obj1 : obj0;
                    const float t = te[e], q = pe[e];
                    const float d = t - q;
                    if (ch >= 5) {
                        scl += obj * d * d;                  // channels 5..105: class
                    } else if (ch < 2) {
                        sxy += obj * d * d;                  // channels 0,1: xy
                    } else if (ch < 4) {
                        const float a = sqrtf(t) - sqrtf(fmaxf(q, 0.f));
                        swh += obj * a * a;                  // channels 2,3: wh (sqrt)
                    } else {                                 // channel 4: confidence
                        sco += obj * d * d;
                        scn += (1.f - obj) * d * d;
                    }
                }
            }
        }
    }

    // warp reduction
    #pragma unroll
    for (int o = 16; o > 0; o >>= 1) {
        sxy += __shfl_xor_sync(0xFFFFFFFFu, sxy, o);
        swh += __shfl_xor_sync(0xFFFFFFFFu, swh, o);
        sco += __shfl_xor_sync(0xFFFFFFFFu, sco, o);
        scn += __shfl_xor_sync(0xFFFFFFFFu, scn, o);
        scl += __shfl_xor_sync(0xFFFFFFFFu, scl, o);
    }
    if (lane == 0) {
        s[wid][0] = sxy; s[wid][1] = swh; s[wid][2] = sco;
        s[wid][3] = scn; s[wid][4] = scl;
    }
    __syncthreads();

    // cross-warp reduce + unconditional partial store (no atomics, no init)
    if (wid == 0 && lane < 5) {
        float v = 0.f;
        #pragma unroll
        for (int w = 0; w < NWPB; ++w) v += s[w][lane];
        g_part[lane * NBLOCKS + blockIdx.x] = v;
    }
}

__global__ void __launch_bounds__(192) yolo_final_kernel(float* __restrict__ out) {
    __shared__ double sd[5];
    const int wid  = threadIdx.x >> 5;   // warp w handles channel w (w < 5)
    const int lane = threadIdx.x & 31;

    if (wid < 5) {
        double v = 0.0;
        for (int b = lane; b < NBLOCKS; b += 32)
            v += (double)g_part[wid * NBLOCKS + b];
        #pragma unroll
        for (int o = 16; o > 0; o >>= 1)
            v += __shfl_xor_sync(0xFFFFFFFFu, v, o);
        if (lane == 0) sd[wid] = v;
    }
    __syncthreads();

    if (threadIdx.x == 0) {
        const double inv = 1.0 / BATCH;
        const double lxy = sd[0] * inv;
        const double lwh = sd[1] * inv;
        const double lco = sd[2] * inv;
        const double lcn = sd[3] * inv;
        const double lcl = sd[4] * inv;
        const double loss = (5.0 * lxy + 5.0 * lwh + lco + 0.5 * lcn + lcl) * inv;
        out[0] = (float)lxy;
        out[1] = (float)lwh;
        out[2] = (float)lco;
        out[3] = (float)lcn;
        out[4] = (float)lcl;
        out[5] = (float)loss;
    }
}

extern "C" void kernel_launch(void* const* d_in, const int* in_sizes, int n_in,
                              void* d_out, int out_size) {
    const float* pred = (const float*)d_in[0];
    const float* targ = (const float*)d_in[1];
    float* out = (float*)d_out;

    yolo_reduce_kernel<<<NBLOCKS, 256>>>(pred, targ);
    yolo_final_kernel<<<1, 192>>>(out);
}